// round 13
// baseline (speedup 1.0000x reference)
#include <cuda_runtime.h>
#include <cuda_fp16.h>
#include <cstdint>

// Problem constants
#define Bc   1024
#define Tc   512
#define EMBc 100
#define H1c  128
#define G1c  512   // 4*H1
#define H2c  64
#define G2c  256   // 4*H2

// ---------------------------------------------------------------------------
// helpers
// ---------------------------------------------------------------------------
__device__ __forceinline__ uint32_t s2u(const void* p) {
    return (uint32_t)__cvta_generic_to_shared(p);
}
__device__ __forceinline__ void ldm_x4(uint32_t& a0, uint32_t& a1, uint32_t& a2, uint32_t& a3,
                                       uint32_t addr) {
    asm volatile("ldmatrix.sync.aligned.m8n8.x4.shared.b16 {%0,%1,%2,%3}, [%4];"
                 : "=r"(a0), "=r"(a1), "=r"(a2), "=r"(a3) : "r"(addr));
}
__device__ __forceinline__ void ldm_x2(uint32_t& b0, uint32_t& b1, uint32_t addr) {
    asm volatile("ldmatrix.sync.aligned.m8n8.x2.shared.b16 {%0,%1}, [%2];"
                 : "=r"(b0), "=r"(b1) : "r"(addr));
}
__device__ __forceinline__ void mma16816(float* d, const uint32_t* a, const uint32_t* b) {
    asm volatile("mma.sync.aligned.m16n8k16.row.col.f32.f16.f16.f32 "
                 "{%0,%1,%2,%3}, {%4,%5,%6,%7}, {%8,%9}, {%0,%1,%2,%3};"
                 : "+f"(d[0]), "+f"(d[1]), "+f"(d[2]), "+f"(d[3])
                 : "r"(a[0]), "r"(a[1]), "r"(a[2]), "r"(a[3]), "r"(b[0]), "r"(b[1]));
}
__device__ __forceinline__ float tanhfast(float x) {
    float y;
    asm("tanh.approx.f32 %0, %1;" : "=f"(y) : "f"(x));
    return y;
}
__device__ __forceinline__ float sigfast(float x) {
    return 0.5f * tanhfast(0.5f * x) + 0.5f;
}
__device__ __forceinline__ uint32_t packh2(float x, float y) {
    __half2 h = __floats2half2_rn(x, y);
    return *reinterpret_cast<uint32_t*>(&h);
}

// ---------------------------------------------------------------------------
// Smem layout (bytes)
// ---------------------------------------------------------------------------
#define W1S 120                         // W1_ih row stride (halves), conflict-free
#define W2S 136                         // W2_ih row stride (halves)
#define XTS 120                         // X tile row stride (halves), conflict-free
#define HP1f 136
#define HP2f 72

#define OFF_W1   0
#define SZ_W1    (512 * W1S * 2)        // 122880
#define OFF_W2I  (OFF_W1 + SZ_W1)
#define SZ_W2I   (256 * W2S * 2)        // 69632
#define OFF_XT   (OFF_W2I + SZ_W2I)
#define SZ_XT    (2 * 8 * XTS * 2)      // 3840
#define OFF_H1   (OFF_XT + SZ_XT)
#define SZ_H1    (2 * 8 * HP1f * 2)     // 4352
#define OFF_H2   (OFF_H1 + SZ_H1)
#define SZ_H2    (2 * 8 * HP2f * 2)     // 2304
#define OFF_HF   (OFF_H2 + SZ_H2)
#define SZ_HF    (8 * 64 * 4)           // 2048
#define SMEMF    (OFF_HF + SZ_HF)       // 205056

// ---------------------------------------------------------------------------
// ONE kernel: input projection + layer-1 recurrence + layer-2 recurrence + FC.
// 128 blocks x 512 threads, 8 batch rows/block. Per iteration t:
//   h1[t] = LSTM1(x_t, h1[t-1])   gates = b1 + W1ih@x_t + W1hh@h1[t-1] (MMA)
//   h2[t-1] = LSTM2(h1[t-1], h2[t-2])  (1-step software pipeline)
// bf1 fragments of h1[t-1] shared by L1-hh and L2-ih MMAs.
// W1hh: 64 persistent regs. W2hh: 16 persistent regs. W1ih, W2ih: smem
// (permuted rows -> direct ldm_x4 A-frags). X: fp32 LDG.128 one step ahead,
// cvt->fp16 tile by the loading thread itself (single barrier per step).
// ---------------------------------------------------------------------------
__global__ void __launch_bounds__(512) rnn_all_kernel(
    const float* __restrict__ X,      // [B][T][100]
    const float* __restrict__ W1ih,   // [512][100]
    const float* __restrict__ W1hh,   // [512][128]
    const float* __restrict__ b1_ih,
    const float* __restrict__ b1_hh,
    const float* __restrict__ W2ih,   // [256][128]
    const float* __restrict__ W2hh,   // [256][64]
    const float* __restrict__ b2_ih,
    const float* __restrict__ b2_hh,
    const float* __restrict__ fc1w,
    const float* __restrict__ fc1b,
    const float* __restrict__ fc2w,
    const float* __restrict__ fc2b,
    float* __restrict__ out)
{
    extern __shared__ char smraw[];
    __half* W1s  = (__half*)(smraw + OFF_W1);
    __half* W2is = (__half*)(smraw + OFF_W2I);
    __half* Xt   = (__half*)(smraw + OFF_XT);
    __half* hsh1 = (__half*)(smraw + OFF_H1);
    __half* hsh2 = (__half*)(smraw + OFF_H2);
    float*  hfin = (float*)(smraw + OFF_HF);

    const int tid  = threadIdx.x;
    const int w    = tid >> 5;
    const int lane = tid & 31;
    const int b0   = blockIdx.x * 8;
    const int r    = lane >> 2;
    const int q    = lane & 3;
    const int n0   = q * 2;
    const bool lo  = (r < 4);
    const int ncol = n0 + (lo ? 0 : 1);

    // ---- L1 mapping (16 warps x 2 m16 tiles, gate-permuted) ----
    int uu[2], Glo1[2], Ghi1[2];
#pragma unroll
    for (int mt = 0; mt < 2; mt++) {
        uu[mt]   = w * 8 + mt * 4 + (r & 3);
        Glo1[mt] = (r >> 2) * H1c + uu[mt];
        Ghi1[mt] = ((r + 8) >> 2) * H1c + uu[mt];
    }
    // persistent W1_hh fragments (64 regs)
    uint32_t afr[2][8][4];
#pragma unroll
    for (int mt = 0; mt < 2; mt++) {
        const float* rl = W1hh + (size_t)Glo1[mt] * H1c;
        const float* rh = W1hh + (size_t)Ghi1[mt] * H1c;
#pragma unroll
        for (int ks = 0; ks < 8; ks++) {
            int k = ks * 16 + q * 2;
            afr[mt][ks][0] = packh2(rl[k],     rl[k + 1]);
            afr[mt][ks][1] = packh2(rh[k],     rh[k + 1]);
            afr[mt][ks][2] = packh2(rl[k + 8], rl[k + 9]);
            afr[mt][ks][3] = packh2(rh[k + 8], rh[k + 9]);
        }
    }
    // L1 biases folded into accumulator init
    float b1lo[2], b1hi[2];
#pragma unroll
    for (int mt = 0; mt < 2; mt++) {
        b1lo[mt] = __ldg(b1_ih + Glo1[mt]) + __ldg(b1_hh + Glo1[mt]);
        b1hi[mt] = __ldg(b1_ih + Ghi1[mt]) + __ldg(b1_hh + Ghi1[mt]);
    }

    // ---- L2 mapping ----
    const int u    = w * 4 + (r & 3);
    const int Glo2 = (r >> 2) * H2c + u;
    const int Ghi2 = ((r + 8) >> 2) * H2c + u;
    const float b2lo = __ldg(b2_ih + Glo2) + __ldg(b2_hh + Glo2);
    const float b2hi = __ldg(b2_ih + Ghi2) + __ldg(b2_hh + Ghi2);
    // persistent W2_hh fragments (16 regs)
    uint32_t ahh[4][4];
    {
        const float* rl = W2hh + (size_t)Glo2 * H2c;
        const float* rh = W2hh + (size_t)Ghi2 * H2c;
#pragma unroll
        for (int ks = 0; ks < 4; ks++) {
            int k = ks * 16 + q * 2;
            ahh[ks][0] = packh2(rl[k],     rl[k + 1]);
            ahh[ks][1] = packh2(rh[k],     rh[k + 1]);
            ahh[ks][2] = packh2(rl[k + 8], rl[k + 9]);
            ahh[ks][3] = packh2(rh[k + 8], rh[k + 9]);
        }
    }

    // ---- stage W1_ih into smem, permuted rows, fp16, zero-pad k>=100 ----
    for (int idx = tid; idx < 512 * 112; idx += 512) {
        int tr = idx / 112, k = idx - tr * 112;
        int tile = tr >> 4, pr = tr & 15;
        int u0 = (tile >> 1) * 8 + (tile & 1) * 4;
        int src = (pr >> 2) * H1c + u0 + (pr & 3);
        float v = (k < EMBc) ? W1ih[(size_t)src * EMBc + k] : 0.f;
        W1s[tr * W1S + k] = __float2half_rn(v);
    }
    // ---- stage W2_ih into smem, permuted rows ----
    for (int idx = tid; idx < 256 * 128; idx += 512) {
        int tr = idx >> 7, k = idx & 127;
        int pr = tr & 15, ww = tr >> 4;
        int src = (pr >> 2) * H2c + ww * 4 + (pr & 3);
        W2is[tr * W2S + k] = __float2half_rn(W2ih[(size_t)src * H1c + k]);
    }
    // zero h states + X tiles (both buffers; X pad cols [100,112) stay 0)
    for (int i = tid; i < 2 * 8 * HP1f / 2; i += 512)
        ((__half2*)hsh1)[i] = __floats2half2_rn(0.f, 0.f);
    for (int i = tid; i < 2 * 8 * HP2f / 2; i += 512)
        ((__half2*)hsh2)[i] = __floats2half2_rn(0.f, 0.f);
    for (int i = tid; i < 2 * 8 * XTS / 2; i += 512)
        ((__half2*)Xt)[i] = __floats2half2_rn(0.f, 0.f);

    // ---- X loader identity: threads 0..199, 8 rows x 25 float4 chunks ----
    const int xrow = tid / 25;         // 0..7 (tid<200)
    const int xc   = tid - xrow * 25;  // 0..24
    const float* xrp = X + ((size_t)(b0 + xrow) * Tc) * EMBc + xc * 4;
    // prologue: load + convert X[t=0]
    if (tid < 200) {
        float4 v = *(const float4*)(xrp);
        uint2 p;
        p.x = packh2(v.x, v.y);
        p.y = packh2(v.z, v.w);
        *(uint2*)&Xt[0 * 8 * XTS + xrow * XTS + xc * 4] = p;
    }
    __syncthreads();

    // precomputed smem byte-addresses for A-frag ldm_x4
    const uint32_t aW1_base0 = s2u(W1s + (w * 32 + (lane & 15)) * W1S + (lane >> 4) * 8);
    const uint32_t aW1_base1 = aW1_base0 + 16 * W1S * 2;
    const uint32_t aih_base  = s2u(W2is + (w * 16 + (lane & 15)) * W2S + (lane >> 4) * 8);

    float cst1[2] = {0.f, 0.f};
    float cst2 = 0.f;
    const int l = lane & 15;

    for (int t = 0; t <= Tc; t++) {
        // early: issue fp32 X loads for t+1 (latency hidden by whole step)
        float4 xv;
        const bool do_x = (tid < 200) && (t + 1 < Tc);
        if (do_x) xv = *(const float4*)(xrp + (size_t)(t + 1) * EMBc);

        const __half* xtb = Xt + (t & 1) * 8 * XTS;
        const __half* hb1 = hsh1 + (t & 1) * 8 * HP1f;
        const __half* hb2 = hsh2 + (t & 1) * 8 * HP2f;

        // B fragments of h1[t-1] — shared by L1-hh and L2-ih
        uint32_t bf1[8][2];
        {
            uint32_t baddr = s2u(hb1 + (l & 7) * HP1f + ((l >> 3) & 1) * 8);
#pragma unroll
            for (int ks = 0; ks < 8; ks++)
                ldm_x2(bf1[ks][0], bf1[ks][1], baddr + ks * 32);
        }

        // ---- L1: h1[t] = LSTM1(x_t, h1[t-1]) ----
        if (t < Tc) {
            // B fragments of x_t
            uint32_t bfX[7][2];
            {
                uint32_t baddr = s2u(xtb + (l & 7) * XTS + ((l >> 3) & 1) * 8);
#pragma unroll
                for (int ks = 0; ks < 7; ks++)
                    ldm_x2(bfX[ks][0], bfX[ks][1], baddr + ks * 32);
            }
            float acc1[2][4];
#pragma unroll
            for (int mt = 0; mt < 2; mt++) {
                acc1[mt][0] = b1lo[mt]; acc1[mt][1] = b1lo[mt];
                acc1[mt][2] = b1hi[mt]; acc1[mt][3] = b1hi[mt];
            }
            // input projection: W1ih @ x_t  (A-frags from smem)
#pragma unroll
            for (int ks = 0; ks < 7; ks++) {
                uint32_t a0[4], a1[4];
                ldm_x4(a0[0], a0[1], a0[2], a0[3], aW1_base0 + ks * 32);
                ldm_x4(a1[0], a1[1], a1[2], a1[3], aW1_base1 + ks * 32);
                mma16816(acc1[0], a0, bfX[ks]);
                mma16816(acc1[1], a1, bfX[ks]);
            }
            // recurrence: W1hh @ h1[t-1]  (A-frags persistent regs)
#pragma unroll
            for (int ks = 0; ks < 8; ks++) {
                mma16816(acc1[0], afr[0][ks], bf1[ks]);
                mma16816(acc1[1], afr[1][ks], bf1[ks]);
            }
#pragma unroll
            for (int mt = 0; mt < 2; mt++) {
                float s0 = lo ? acc1[mt][1] : acc1[mt][0];
                float s1 = lo ? acc1[mt][3] : acc1[mt][2];
                float r0 = __shfl_xor_sync(0xffffffffu, s0, 16);
                float r1 = __shfl_xor_sync(0xffffffffu, s1, 16);
                float zi = lo ? acc1[mt][0] : r0;
                float zf = lo ? r0          : acc1[mt][1];
                float zg = lo ? acc1[mt][2] : r1;
                float zo = lo ? r1          : acc1[mt][3];

                cst1[mt] = sigfast(zf) * cst1[mt] + sigfast(zi) * tanhfast(zg);
                float h = sigfast(zo) * tanhfast(cst1[mt]);
                hsh1[((t + 1) & 1) * 8 * HP1f + ncol * HP1f + uu[mt]] = __float2half_rn(h);
            }
        }

        // ---- L2: h2[t-1] = LSTM2(h1[t-1], h2[t-2]) ----
        if (t >= 1) {
            uint32_t bf2[4][2];
            {
                uint32_t baddr = s2u(hb2 + (l & 7) * HP2f + ((l >> 3) & 1) * 8);
#pragma unroll
                for (int ks = 0; ks < 4; ks++)
                    ldm_x2(bf2[ks][0], bf2[ks][1], baddr + ks * 32);
            }
            float accA[4] = {b2lo, b2lo, b2hi, b2hi};
            float accC[4] = {0.f, 0.f, 0.f, 0.f};
#pragma unroll
            for (int ks = 0; ks < 8; ks++) {
                uint32_t a2[4];
                ldm_x4(a2[0], a2[1], a2[2], a2[3], aih_base + ks * 32);
                mma16816(accA, a2, bf1[ks]);
            }
#pragma unroll
            for (int ks = 0; ks < 4; ks++)
                mma16816(accC, ahh[ks], bf2[ks]);

            float acc[4];
#pragma unroll
            for (int i = 0; i < 4; i++) acc[i] = accA[i] + accC[i];

            float s0 = lo ? acc[1] : acc[0];
            float s1 = lo ? acc[3] : acc[2];
            float r0 = __shfl_xor_sync(0xffffffffu, s0, 16);
            float r1 = __shfl_xor_sync(0xffffffffu, s1, 16);
            float zi = lo ? acc[0] : r0;
            float zf = lo ? r0     : acc[1];
            float zg = lo ? acc[2] : r1;
            float zo = lo ? r1     : acc[3];

            cst2 = sigfast(zf) * cst2 + sigfast(zi) * tanhfast(zg);
            float h = sigfast(zo) * tanhfast(cst2);

            if (t == Tc) hfin[ncol * 64 + u] = h;
            else hsh2[((t + 1) & 1) * 8 * HP2f + ncol * HP2f + u] = __float2half_rn(h);
        }

        // late: convert own X chunk for t+1 into the fp16 tile
        if (do_x) {
            uint2 p;
            p.x = packh2(xv.x, xv.y);
            p.y = packh2(xv.z, xv.w);
            *(uint2*)&Xt[((t + 1) & 1) * 8 * XTS + xrow * XTS + xc * 4] = p;
        }
        __syncthreads();
    }

    // FC head: warp w -> batch row w (warps 0..7), lane = fc1 unit
    if (w < 8) {
        float a = __ldg(fc1b + lane);
#pragma unroll
        for (int k = 0; k < 64; k++)
            a = fmaf(hfin[w * 64 + k], __ldg(fc1w + lane * 64 + k), a);
        a = fmaxf(a, 0.f);
        float v = a * __ldg(fc2w + lane);
#pragma unroll
        for (int off = 16; off; off >>= 1) v += __shfl_down_sync(0xffffffffu, v, off);
        if (lane == 0) out[b0 + w] = 1.f / (1.f + __expf(-(v + __ldg(fc2b))));
    }
}

// ---------------------------------------------------------------------------
extern "C" void kernel_launch(void* const* d_in, const int* in_sizes, int n_in,
                              void* d_out, int out_size)
{
    (void)in_sizes; (void)n_in; (void)out_size;
    const float* X     = (const float*)d_in[0];
    const float* W1_ih = (const float*)d_in[1];
    const float* W1_hh = (const float*)d_in[2];
    const float* b1_ih = (const float*)d_in[3];
    const float* b1_hh = (const float*)d_in[4];
    const float* W2_ih = (const float*)d_in[5];
    const float* W2_hh = (const float*)d_in[6];
    const float* b2_ih = (const float*)d_in[7];
    const float* b2_hh = (const float*)d_in[8];
    const float* fc1w  = (const float*)d_in[9];
    const float* fc1b  = (const float*)d_in[10];
    const float* fc2w  = (const float*)d_in[11];
    const float* fc2b  = (const float*)d_in[12];
    float* out = (float*)d_out;

    static int attr_done = 0;
    if (!attr_done) {
        cudaFuncSetAttribute(rnn_all_kernel, cudaFuncAttributeMaxDynamicSharedMemorySize, SMEMF);
        attr_done = 1;
    }

    // Entire network in one persistent kernel (no gmem scratch at all).
    rnn_all_kernel<<<Bc / 8, 512, SMEMF>>>(X, W1_ih, W1_hh, b1_ih, b1_hh,
                                           W2_ih, W2_hh, b2_ih, b2_hh,
                                           fc1w, fc1b, fc2w, fc2b, out);
}